// round 15
// baseline (speedup 1.0000x reference)
#include <cuda_runtime.h>
#include <cuda_bf16.h>
#include <math.h>
#include <stdint.h>

// Problem constants
#define BATCH 4
#define SEQ   2048
#define DMODEL 1024
#define NH    16
#define DHD   64
#define MTOT  (BATCH*SEQ)      // 8192
#define N_QKV (3*DMODEL)       // 3072

typedef unsigned short u16;
typedef unsigned int   u32;

// single dynamic-smem declaration shared by all kernels
extern __shared__ char dynsm[];

// ---------------- scratch (static device globals; no allocation) ----------------
__device__ __align__(16) float g_q [(size_t)BATCH*NH*SEQ*DHD];
__device__ __align__(16) float g_k [(size_t)BATCH*NH*SEQ*DHD];
__device__ __align__(16) float g_v [(size_t)BATCH*NH*SEQ*DHD];
__device__ __align__(16) u16 g_xh [(size_t)MTOT*DMODEL];
__device__ __align__(16) u16 g_xl [(size_t)MTOT*DMODEL];
__device__ __align__(16) u16 g_wh [(size_t)N_QKV*DMODEL];
__device__ __align__(16) u16 g_wl [(size_t)N_QKV*DMODEL];
__device__ __align__(16) u16 g_woh[(size_t)DMODEL*DMODEL];
__device__ __align__(16) u16 g_wol[(size_t)DMODEL*DMODEL];
__device__ __align__(16) u16 g_aoh[(size_t)MTOT*DMODEL];
__device__ __align__(16) u16 g_aol[(size_t)MTOT*DMODEL];
__device__ float g_cos[SEQ*32];
__device__ float g_sin[SEQ*32];

// ---------------- helpers ----------------
static __device__ __forceinline__ uint32_t smem_u32(const void* p) {
    uint32_t a;
    asm("{ .reg .u64 t; cvta.to.shared.u64 t, %1; cvt.u32.u64 %0, t; }" : "=r"(a) : "l"(p));
    return a;
}
// bf16 hi/lo split: x = hi + lo + O(2^-18 x)
static __device__ __forceinline__ void split1(float x, u16& h, u16& l) {
    __nv_bfloat16 hb = __float2bfloat16_rn(x);
    float hf = __bfloat162float(hb);
    __nv_bfloat16 lb = __float2bfloat16_rn(x - hf);
    h = __bfloat16_as_ushort(hb);
    l = __bfloat16_as_ushort(lb);
}
// split two floats -> packed bf16x2 hi + packed bf16x2 lo
static __device__ __forceinline__ void pksplit(float a, float b, u32& h, u32& l) {
    u16 ha, la, hb, lb;
    split1(a, ha, la);
    split1(b, hb, lb);
    h = (u32)ha | ((u32)hb << 16);
    l = (u32)la | ((u32)lb << 16);
}
static __device__ __forceinline__ void ldmx4(uint32_t* r, uint32_t a) {
    asm volatile("ldmatrix.sync.aligned.m8n8.x4.shared.b16 {%0,%1,%2,%3}, [%4];"
        : "=r"(r[0]), "=r"(r[1]), "=r"(r[2]), "=r"(r[3]) : "r"(a));
}
static __device__ __forceinline__ void ldmx4t(uint32_t* r, uint32_t a) {
    asm volatile("ldmatrix.sync.aligned.m8n8.x4.trans.shared.b16 {%0,%1,%2,%3}, [%4];"
        : "=r"(r[0]), "=r"(r[1]), "=r"(r[2]), "=r"(r[3]) : "r"(a));
}
static __device__ __forceinline__ void mma_bf16(float* c, const uint32_t* a, const uint32_t* b) {
    asm volatile("mma.sync.aligned.m16n8k16.row.col.f32.bf16.bf16.f32 "
        "{%0,%1,%2,%3}, {%4,%5,%6,%7}, {%8,%9}, {%0,%1,%2,%3};"
        : "+f"(c[0]), "+f"(c[1]), "+f"(c[2]), "+f"(c[3])
        : "r"(a[0]), "r"(a[1]), "r"(a[2]), "r"(a[3]), "r"(b[0]), "r"(b[1]));
}
// cp.async (LDGSTS)
static __device__ __forceinline__ void cpa16(uint32_t d, const void* s) {
    asm volatile("cp.async.cg.shared.global [%0], [%1], 16;" :: "r"(d), "l"(s) : "memory");
}
static __device__ __forceinline__ void cp_commit() {
    asm volatile("cp.async.commit_group;" ::: "memory");
}
template<int N> static __device__ __forceinline__ void cp_wait() {
    asm volatile("cp.async.wait_group %0;" :: "n"(N) : "memory");
}

// ---------------- RoPE tables ----------------
__global__ void rope_table_kernel() {
    int idx = blockIdx.x * blockDim.x + threadIdx.x;
    if (idx >= SEQ * 32) return;
    int s = idx >> 5;
    int j = idx & 31;
    float invf = exp2f(-(float)j * 0.41524101186092f);  // 10000^(-j/32)
    float ang  = (float)s * invf;
    g_cos[idx] = (float)cos((double)ang);
    g_sin[idx] = (float)sin((double)ang);
}

// ---------------- bf16 hi/lo pre-split kernels ----------------
static __device__ __forceinline__ void cvt_body(const float* __restrict__ src,
                                                u16* __restrict__ dh, u16* __restrict__ dl, int n4) {
    int i = blockIdx.x * blockDim.x + threadIdx.x;
    if (i >= n4) return;
    float4 v = ((const float4*)src)[i];
    u16 h0,h1,h2,h3,l0,l1,l2,l3;
    split1(v.x,h0,l0); split1(v.y,h1,l1); split1(v.z,h2,l2); split1(v.w,h3,l3);
    ((uint2*)dh)[i] = make_uint2((u32)h0 | ((u32)h1<<16), (u32)h2 | ((u32)h3<<16));
    ((uint2*)dl)[i] = make_uint2((u32)l0 | ((u32)l1<<16), (u32)l2 | ((u32)l3<<16));
}
__global__ void cvt_x_kernel (const float* __restrict__ s){ cvt_body(s, g_xh,  g_xl,  MTOT*DMODEL/4); }
__global__ void cvt_w_kernel (const float* __restrict__ s){ cvt_body(s, g_wh,  g_wl,  N_QKV*DMODEL/4); }
__global__ void cvt_wo_kernel(const float* __restrict__ s){ cvt_body(s, g_woh, g_wol, DMODEL*DMODEL/4); }

// ============================================================================
// bf16-split mma.sync GEMM: C[128,128] = A[m0:,K] * B[n0:,K]^T, K=1024.
// cp.async 2-stage pipeline (operands pre-split in gmem), 8 warps (2m x 4n),
// warp tile 64x32, k-chunk 32. Row stride 80B (conflict-free, validated R12).
// ============================================================================
#define MM_BUF  40960
#define MM_SMEM 81920

__device__ __forceinline__ void mma_mainloop(
    const u16* __restrict__ Ah, const u16* __restrict__ Al,
    const u16* __restrict__ Bh, const u16* __restrict__ Bl,
    int m0, int n0, char* sm, uint32_t smb, float c[4][4][4])
{
    const int tid  = threadIdx.x;
    const int lane = tid & 31;
    const int wid  = tid >> 5;
    const int wm   = wid >> 2;       // 0..1
    const int wn   = wid & 3;        // 0..3
    const int r    = tid & 127;

    // warps 0-3 copy A rows, warps 4-7 copy B rows (one row per thread)
    const char *gb_h, *gb_l;
    uint32_t sdst;
    if (tid < 128) {
        gb_h = (const char*)(Ah + (size_t)(m0 + r) * DMODEL);
        gb_l = (const char*)(Al + (size_t)(m0 + r) * DMODEL);
        sdst = smb + (uint32_t)(r * 80);
    } else {
        gb_h = (const char*)(Bh + (size_t)(n0 + r) * DMODEL);
        gb_l = (const char*)(Bl + (size_t)(n0 + r) * DMODEL);
        sdst = smb + 20480u + (uint32_t)(r * 80);
    }

    // ldmatrix per-lane addressing (validated R12)
    const int arow = (lane & 7) + ((lane >> 3) & 1) * 8;
    const int acol = (lane >> 4) * 16;
    const int brow = (lane & 7) + ((lane >> 4) & 1) * 8;
    const int bcol = ((lane >> 3) & 1) * 16;
    const uint32_t aBase = smb + (uint32_t)((wm*64 + arow) * 80 + acol);
    const uint32_t bBase = smb + 20480 + (uint32_t)((wn*32 + brow) * 80 + bcol);

    // prologue: chunk 0 -> buffer 0
#pragma unroll
    for (int i = 0; i < 4; ++i) {
        cpa16(sdst + i*16, gb_h + i*16);
        cpa16(sdst + 10240 + i*16, gb_l + i*16);
    }
    cp_commit();

    for (int ch = 0; ch < 32; ++ch) {
        const int b = ch & 1;
        const bool nxt = (ch + 1 < 32);
        if (nxt) {
            uint32_t d = sdst + (uint32_t)((b ^ 1) * MM_BUF);
            const char* sh = gb_h + (ch + 1) * 64;
            const char* sl = gb_l + (ch + 1) * 64;
#pragma unroll
            for (int i = 0; i < 4; ++i) {
                cpa16(d + i*16, sh + i*16);
                cpa16(d + 10240 + i*16, sl + i*16);
            }
            cp_commit();
            cp_wait<1>();
        } else {
            cp_wait<0>();
        }
        __syncthreads();

        const uint32_t bo = (uint32_t)(b * MM_BUF);
#pragma unroll
        for (int s = 0; s < 2; ++s) {
            uint32_t ah[4][4], al[4][4], bh[4][2], bl[4][2];
#pragma unroll
            for (int mt = 0; mt < 4; ++mt) {
                ldmx4(ah[mt], aBase + bo + mt*1280 + s*32);
                ldmx4(al[mt], aBase + bo + mt*1280 + s*32 + 10240);
            }
#pragma unroll
            for (int p = 0; p < 2; ++p) {
                uint32_t t4[4];
                ldmx4(t4, bBase + bo + p*1280 + s*32);
                bh[2*p][0] = t4[0]; bh[2*p][1] = t4[1];
                bh[2*p+1][0] = t4[2]; bh[2*p+1][1] = t4[3];
                ldmx4(t4, bBase + bo + p*1280 + s*32 + 10240);
                bl[2*p][0] = t4[0]; bl[2*p][1] = t4[1];
                bl[2*p+1][0] = t4[2]; bl[2*p+1][1] = t4[3];
            }
#pragma unroll
            for (int mt = 0; mt < 4; ++mt)
#pragma unroll
                for (int nt = 0; nt < 4; ++nt) {
                    mma_bf16(c[mt][nt], ah[mt], bh[nt]);
                    mma_bf16(c[mt][nt], ah[mt], bl[nt]);
                    mma_bf16(c[mt][nt], al[mt], bh[nt]);
                }
        }
        __syncthreads();   // buffer b free for reuse at iter ch+1's issue
    }
}

// store fragments to Cs[128][132]
__device__ __forceinline__ void frag_to_cs(float* Cs, float c[4][4][4]) {
    const int tid = threadIdx.x;
    const int lane = tid & 31;
    const int wid = tid >> 5;
    const int wm = wid >> 2, wn = wid & 3;
    const int tr = lane >> 2, tc = (lane & 3) * 2;
#pragma unroll
    for (int mt = 0; mt < 4; ++mt)
#pragma unroll
        for (int nt = 0; nt < 4; ++nt) {
            int rr = wm*64 + mt*16 + tr;
            int cc = wn*32 + nt*8 + tc;
            *(float2*)&Cs[rr*132 + cc]       = make_float2(c[mt][nt][0], c[mt][nt][1]);
            *(float2*)&Cs[(rr+8)*132 + cc]   = make_float2(c[mt][nt][2], c[mt][nt][3]);
        }
    __syncthreads();
}

// ---------------- QKV GEMM (mma.sync) + RoPE epilogue ----------------
__global__ __launch_bounds__(256, 2) void qkv_mma_kernel()
{
    char* sm = dynsm;
    uint32_t smb = smem_u32(sm);

    float c[4][4][4];
#pragma unroll
    for (int a = 0; a < 4; ++a)
#pragma unroll
        for (int b = 0; b < 4; ++b)
#pragma unroll
            for (int d = 0; d < 4; ++d) c[a][b][d] = 0.f;

    const int m0 = blockIdx.x * 128;
    const int nt = blockIdx.y;                  // 0..23
    mma_mainloop(g_xh, g_xl, g_wh, g_wl, m0, nt * 128, sm, smb, c);

    float* Cs = (float*)sm;
    frag_to_cs(Cs, c);

    const int tid = threadIdx.x;
    const int sel   = nt >> 3;                  // 0=Q 1=K 2=V
    const int hbase = (nt & 7) * 2;
    float* dst = (sel == 0) ? g_q : ((sel == 1) ? g_k : g_v);

    for (int e = tid; e < 8192; e += 256) {
        int rr = e >> 6;
        int d  = (e & 63) * 2;                  // even col 0..126
        int m = m0 + rr;
        int b = m >> 11, s = m & 2047;
        float2 v = *(float2*)&Cs[rr*132 + d];
        int head = hbase + (d >> 6);
        int dloc = d & 63;
        if (sel < 2) {
            float2 p = *(float2*)&Cs[rr*132 + (d ^ 32)];
            int j = d & 31;
            float c0 = g_cos[s*32 + j],   c1 = g_cos[s*32 + j + 1];
            float s0 = g_sin[s*32 + j],   s1 = g_sin[s*32 + j + 1];
            if (dloc < 32) { v.x = v.x*c0 - p.x*s0; v.y = v.y*c1 - p.y*s1; }
            else           { v.x = v.x*c0 + p.x*s0; v.y = v.y*c1 + p.y*s1; }
        }
        *(float2*)&dst[(((size_t)b*NH + head)*SEQ + s)*DHD + dloc] = v;
    }
}

// ---------------- out_proj (mma.sync): out = AO @ wo^T ----------------
__global__ __launch_bounds__(256, 2) void out_proj_mma_kernel(float* __restrict__ out)
{
    char* sm = dynsm;
    uint32_t smb = smem_u32(sm);

    float c[4][4][4];
#pragma unroll
    for (int a = 0; a < 4; ++a)
#pragma unroll
        for (int b = 0; b < 4; ++b)
#pragma unroll
            for (int d = 0; d < 4; ++d) c[a][b][d] = 0.f;

    const int m0 = blockIdx.x * 128;
    const int n0 = blockIdx.y * 128;
    mma_mainloop(g_aoh, g_aol, g_woh, g_wol, m0, n0, sm, smb, c);

    float* Cs = (float*)sm;
    frag_to_cs(Cs, c);

    const int tid = threadIdx.x;
    for (int e = tid; e < 4096; e += 256) {
        int rr = e >> 5;
        int d4 = (e & 31) * 4;
        *(float4*)&out[(size_t)(m0 + rr)*DMODEL + n0 + d4] = *(float4*)&Cs[rr*132 + d4];
    }
}

// ============================================================================
// Flash attention on mma.sync (causal). BM=128 (8 warps x m16), KV tile 64.
// S = QK^T 3-term bf16 split; softmax on C-fragments in registers;
// P packed in-register (C-frag == A-frag layout); P@V 3-term with V stored
// row-major [c][d] and B-fragments from ldmatrix.x4.trans.
// smem rows stride 144B (ldmatrix banks 4r mod 32 -> conflict-free).
// ============================================================================
#define AQH 0
#define AQL 18432
#define AKH 36864
#define AKL 46080
#define AVH 55296
#define AVL 64512
#define ATTN_SMEM 73728

__global__ __launch_bounds__(256, 2) void attn_mma_kernel()
{
    char* sm = dynsm;
    uint32_t smb = smem_u32(sm);

    const int tid  = threadIdx.x;
    const int lane = tid & 31;
    const int wid  = tid >> 5;          // 0..7, warp owns q-rows 16*wid..+15
    const int qt   = blockIdx.x;        // 0..15 (128-row q tile)
    const int bh   = blockIdx.y;        // 0..63

    const float* Qg = g_q + ((size_t)bh * SEQ + qt * 128) * DHD;
    const float* Kg = g_k + (size_t)bh * SEQ * DHD;
    const float* Vg = g_v + (size_t)bh * SEQ * DHD;

    // ---- load Q tile 128x64, scale by 1/8, split hi/lo into smem ----
    for (int slot = tid; slot < 2048; slot += 256) {
        int r  = slot >> 4;
        int f4 = slot & 15;
        float4 v = ((const float4*)Qg)[slot];
        v.x *= 0.125f; v.y *= 0.125f; v.z *= 0.125f; v.w *= 0.125f;
        u32 h0, l0, h1, l1;
        pksplit(v.x, v.y, h0, l0);
        pksplit(v.z, v.w, h1, l1);
        *(uint2*)(sm + AQH + r*144 + f4*8) = make_uint2(h0, h1);
        *(uint2*)(sm + AQL + r*144 + f4*8) = make_uint2(l0, l1);
    }

    // ldmatrix lane addressing
    const int arow = (lane & 7) + ((lane >> 3) & 1) * 8;
    const int acol = (lane >> 4) * 16;
    const int brow = (lane & 7) + ((lane >> 4) & 1) * 8;
    const int bcol = ((lane >> 3) & 1) * 16;
    const uint32_t aBaseH = smb + AQH + (uint32_t)((wid*16 + arow)*144 + acol);
    const uint32_t aBaseL = aBaseH + (AQL - AQH);
    const uint32_t kBase  = smb + AKH + (uint32_t)(brow*144 + bcol);
    // trans-ldmatrix addressing for V[c][d]: row = c (k), col-block = d (n)
    const int vrow = (lane & 7) + ((lane >> 3) & 1) * 8;
    const int vcol = ((lane >> 4) & 1) * 16;
    const uint32_t vBase  = smb + AVH + (uint32_t)(vrow*144 + vcol);

    const int rowTop = qt*128 + wid*16;
    const int r0     = rowTop + (lane >> 2);

    float mi0 = -INFINITY, mi1 = -INFINITY, li0 = 0.f, li1 = 0.f;
    float accO[8][4];
#pragma unroll
    for (int j = 0; j < 8; ++j)
#pragma unroll
        for (int d = 0; d < 4; ++d) accO[j][d] = 0.f;

    const int nkt = 2*qt + 2;
    for (int kt = 0; kt < nkt; ++kt) {
        __syncthreads();     // prior tile's smem reads complete
        // ---- load K and V tiles (64x64 fp32), split; both row-major ----
        for (int slot = tid; slot < 2048; slot += 256) {
            int cc = (slot & 1023) >> 4;
            int f4 = slot & 15;
            if (slot < 1024) {
                float4 v = ((const float4*)(Kg + (size_t)(kt*64 + cc)*DHD))[f4];
                u32 h0, l0, h1, l1;
                pksplit(v.x, v.y, h0, l0);
                pksplit(v.z, v.w, h1, l1);
                *(uint2*)(sm + AKH + cc*144 + f4*8) = make_uint2(h0, h1);
                *(uint2*)(sm + AKL + cc*144 + f4*8) = make_uint2(l0, l1);
            } else {
                float4 v = ((const float4*)(Vg + (size_t)(kt*64 + cc)*DHD))[f4];
                u32 h0, l0, h1, l1;
                pksplit(v.x, v.y, h0, l0);
                pksplit(v.z, v.w, h1, l1);
                *(uint2*)(sm + AVH + cc*144 + f4*8) = make_uint2(h0, h1);
                *(uint2*)(sm + AVL + cc*144 + f4*8) = make_uint2(l0, l1);
            }
        }
        __syncthreads();

        // ---- S = (Q/8) K^T : 3-term bf16 ----
        float accS[8][4];
#pragma unroll
        for (int j = 0; j < 8; ++j)
#pragma unroll
            for (int d = 0; d < 4; ++d) accS[j][d] = 0.f;

#pragma unroll
        for (int s = 0; s < 4; ++s) {
            u32 ah[4], al[4];
            ldmx4(ah, aBaseH + s*32);
            ldmx4(al, aBaseL + s*32);
#pragma unroll
            for (int g = 0; g < 4; ++g) {
                u32 th[4], tl[4];
                ldmx4(th, kBase + g*2304 + s*32);
                ldmx4(tl, kBase + (AKL-AKH) + g*2304 + s*32);
                mma_bf16(accS[2*g],   ah, th);
                mma_bf16(accS[2*g],   ah, tl);
                mma_bf16(accS[2*g],   al, th);
                mma_bf16(accS[2*g+1], ah, th+2);
                mma_bf16(accS[2*g+1], ah, tl+2);
                mma_bf16(accS[2*g+1], al, th+2);
            }
        }

        // ---- causal mask (only tiles crossing the diagonal) ----
        if (kt*64 + 63 > rowTop) {
#pragma unroll
            for (int j = 0; j < 8; ++j) {
                int cb = kt*64 + j*8 + 2*(lane & 3);
                if (cb     > r0)     accS[j][0] = -INFINITY;
                if (cb + 1 > r0)     accS[j][1] = -INFINITY;
                if (cb     > r0 + 8) accS[j][2] = -INFINITY;
                if (cb + 1 > r0 + 8) accS[j][3] = -INFINITY;
            }
        }

        // ---- online softmax on fragments (rows r0, r0+8) ----
        float mx0 = -INFINITY, mx1 = -INFINITY;
#pragma unroll
        for (int j = 0; j < 8; ++j) {
            mx0 = fmaxf(mx0, fmaxf(accS[j][0], accS[j][1]));
            mx1 = fmaxf(mx1, fmaxf(accS[j][2], accS[j][3]));
        }
        mx0 = fmaxf(mx0, __shfl_xor_sync(0xffffffffu, mx0, 1));
        mx0 = fmaxf(mx0, __shfl_xor_sync(0xffffffffu, mx0, 2));
        mx1 = fmaxf(mx1, __shfl_xor_sync(0xffffffffu, mx1, 1));
        mx1 = fmaxf(mx1, __shfl_xor_sync(0xffffffffu, mx1, 2));
        float nm0 = fmaxf(mi0, mx0), nm1 = fmaxf(mi1, mx1);
        float a0 = __expf(mi0 - nm0), a1 = __expf(mi1 - nm1);
        mi0 = nm0; mi1 = nm1;
        float s0 = 0.f, s1 = 0.f;
#pragma unroll
        for (int j = 0; j < 8; ++j) {
            accS[j][0] = __expf(accS[j][0] - nm0); s0 += accS[j][0];
            accS[j][1] = __expf(accS[j][1] - nm0); s0 += accS[j][1];
            accS[j][2] = __expf(accS[j][2] - nm1); s1 += accS[j][2];
            accS[j][3] = __expf(accS[j][3] - nm1); s1 += accS[j][3];
        }
        s0 += __shfl_xor_sync(0xffffffffu, s0, 1);
        s0 += __shfl_xor_sync(0xffffffffu, s0, 2);
        s1 += __shfl_xor_sync(0xffffffffu, s1, 1);
        s1 += __shfl_xor_sync(0xffffffffu, s1, 2);
        li0 = li0 * a0 + s0;
        li1 = li1 * a1 + s1;
#pragma unroll
        for (int j = 0; j < 8; ++j) {
            accO[j][0] *= a0; accO[j][1] *= a0;
            accO[j][2] *= a1; accO[j][3] *= a1;
        }

        // ---- O += P @ V : P from registers, V B-frags via ldmatrix.trans ----
#pragma unroll
        for (int t = 0; t < 4; ++t) {
            u32 ph[4], pl[4];
            pksplit(accS[2*t][0],   accS[2*t][1],   ph[0], pl[0]);
            pksplit(accS[2*t][2],   accS[2*t][3],   ph[1], pl[1]);
            pksplit(accS[2*t+1][0], accS[2*t+1][1], ph[2], pl[2]);
            pksplit(accS[2*t+1][2], accS[2*t+1][3], ph[3], pl[3]);
#pragma unroll
            for (int g = 0; g < 4; ++g) {
                u32 th[4], tl[4];
                ldmx4t(th, vBase + t*2304 + g*32);
                ldmx4t(tl, vBase + (AVL-AVH) + t*2304 + g*32);
                mma_bf16(accO[2*g],   ph, th);
                mma_bf16(accO[2*g],   ph, tl);
                mma_bf16(accO[2*g],   pl, th);
                mma_bf16(accO[2*g+1], ph, th+2);
                mma_bf16(accO[2*g+1], ph, tl+2);
                mma_bf16(accO[2*g+1], pl, th+2);
            }
        }
    }

    // ---- epilogue: normalize, split to bf16 hi/lo for out_proj ----
    const float inv0 = 1.0f / li0, inv1 = 1.0f / li1;
    const int b = bh >> 4, h = bh & 15;
    const int srow = qt*128 + wid*16 + (lane >> 2);
    const size_t base0 = ((size_t)b*SEQ + srow)*DMODEL + h*DHD + 2*(lane & 3);
    const size_t base1 = base0 + (size_t)8*DMODEL;
#pragma unroll
    for (int j = 0; j < 8; ++j) {
        u32 hh, ll;
        pksplit(accO[j][0]*inv0, accO[j][1]*inv0, hh, ll);
        *(u32*)&g_aoh[base0 + j*8] = hh;
        *(u32*)&g_aol[base0 + j*8] = ll;
        pksplit(accO[j][2]*inv1, accO[j][3]*inv1, hh, ll);
        *(u32*)&g_aoh[base1 + j*8] = hh;
        *(u32*)&g_aol[base1 + j*8] = ll;
    }
}

// ---------------- launch ----------------
extern "C" void kernel_launch(void* const* d_in, const int* in_sizes, int n_in,
                              void* d_out, int out_size)
{
    (void)in_sizes; (void)n_in; (void)out_size;
    const float* x    = (const float*)d_in[0];
    const float* qkvw = (const float*)d_in[1];
    const float* wo   = (const float*)d_in[2];
    float*       out  = (float*)d_out;

    rope_table_kernel<<<(SEQ*32 + 255)/256, 256>>>();
    cvt_x_kernel <<<(MTOT*DMODEL/4   + 255)/256, 256>>>(x);
    cvt_w_kernel <<<(N_QKV*DMODEL/4  + 255)/256, 256>>>(qkvw);
    cvt_wo_kernel<<<(DMODEL*DMODEL/4 + 255)/256, 256>>>(wo);

    cudaFuncSetAttribute(qkv_mma_kernel, cudaFuncAttributeMaxDynamicSharedMemorySize, MM_SMEM);
    qkv_mma_kernel<<<dim3(MTOT/128, N_QKV/128), 256, MM_SMEM>>>();

    cudaFuncSetAttribute(attn_mma_kernel, cudaFuncAttributeMaxDynamicSharedMemorySize, ATTN_SMEM);
    attn_mma_kernel<<<dim3(SEQ/128, BATCH*NH), 256, ATTN_SMEM>>>();

    cudaFuncSetAttribute(out_proj_mma_kernel, cudaFuncAttributeMaxDynamicSharedMemorySize, MM_SMEM);
    out_proj_mma_kernel<<<dim3(MTOT/128, DMODEL/128), 256, MM_SMEM>>>(out);
}

// round 17
// speedup vs baseline: 1.1480x; 1.1480x over previous
#include <cuda_runtime.h>
#include <cuda_bf16.h>
#include <math.h>
#include <stdint.h>

// Problem constants
#define BATCH 4
#define SEQ   2048
#define DMODEL 1024
#define NH    16
#define DHD   64
#define MTOT  (BATCH*SEQ)      // 8192
#define N_QKV (3*DMODEL)       // 3072

typedef unsigned short u16;
typedef unsigned int   u32;

// single dynamic-smem declaration shared by all kernels
extern __shared__ char dynsm[];

// ---------------- scratch (static device globals; no allocation) ----------------
__device__ __align__(16) float g_q [(size_t)BATCH*NH*SEQ*DHD];
__device__ __align__(16) float g_k [(size_t)BATCH*NH*SEQ*DHD];
__device__ __align__(16) float g_v [(size_t)BATCH*NH*SEQ*DHD];
__device__ __align__(16) u16 g_xh [(size_t)MTOT*DMODEL];
__device__ __align__(16) u16 g_xl [(size_t)MTOT*DMODEL];
__device__ __align__(16) u16 g_wh [(size_t)N_QKV*DMODEL];
__device__ __align__(16) u16 g_wl [(size_t)N_QKV*DMODEL];
__device__ __align__(16) u16 g_woh[(size_t)DMODEL*DMODEL];
__device__ __align__(16) u16 g_wol[(size_t)DMODEL*DMODEL];
__device__ __align__(16) u16 g_aoh[(size_t)MTOT*DMODEL];
__device__ __align__(16) u16 g_aol[(size_t)MTOT*DMODEL];
__device__ float g_cos[SEQ*32];
__device__ float g_sin[SEQ*32];

// ---------------- helpers ----------------
static __device__ __forceinline__ uint32_t smem_u32(const void* p) {
    uint32_t a;
    asm("{ .reg .u64 t; cvta.to.shared.u64 t, %1; cvt.u32.u64 %0, t; }" : "=r"(a) : "l"(p));
    return a;
}
// bf16 hi/lo split: x = hi + lo + O(2^-18 x)
static __device__ __forceinline__ void split1(float x, u16& h, u16& l) {
    __nv_bfloat16 hb = __float2bfloat16_rn(x);
    float hf = __bfloat162float(hb);
    __nv_bfloat16 lb = __float2bfloat16_rn(x - hf);
    h = __bfloat16_as_ushort(hb);
    l = __bfloat16_as_ushort(lb);
}
// split two floats -> packed bf16x2 hi + packed bf16x2 lo
static __device__ __forceinline__ void pksplit(float a, float b, u32& h, u32& l) {
    u16 ha, la, hb, lb;
    split1(a, ha, la);
    split1(b, hb, lb);
    h = (u32)ha | ((u32)hb << 16);
    l = (u32)la | ((u32)lb << 16);
}
static __device__ __forceinline__ void ldmx4(uint32_t* r, uint32_t a) {
    asm volatile("ldmatrix.sync.aligned.m8n8.x4.shared.b16 {%0,%1,%2,%3}, [%4];"
        : "=r"(r[0]), "=r"(r[1]), "=r"(r[2]), "=r"(r[3]) : "r"(a));
}
static __device__ __forceinline__ void ldmx4t(uint32_t* r, uint32_t a) {
    asm volatile("ldmatrix.sync.aligned.m8n8.x4.trans.shared.b16 {%0,%1,%2,%3}, [%4];"
        : "=r"(r[0]), "=r"(r[1]), "=r"(r[2]), "=r"(r[3]) : "r"(a));
}
static __device__ __forceinline__ void mma_bf16(float* c, const uint32_t* a, const uint32_t* b) {
    asm volatile("mma.sync.aligned.m16n8k16.row.col.f32.bf16.bf16.f32 "
        "{%0,%1,%2,%3}, {%4,%5,%6,%7}, {%8,%9}, {%0,%1,%2,%3};"
        : "+f"(c[0]), "+f"(c[1]), "+f"(c[2]), "+f"(c[3])
        : "r"(a[0]), "r"(a[1]), "r"(a[2]), "r"(a[3]), "r"(b[0]), "r"(b[1]));
}

// ---------------- RoPE tables ----------------
__global__ void rope_table_kernel() {
    int idx = blockIdx.x * blockDim.x + threadIdx.x;
    if (idx >= SEQ * 32) return;
    int s = idx >> 5;
    int j = idx & 31;
    float invf = exp2f(-(float)j * 0.41524101186092f);  // 10000^(-j/32)
    float ang  = (float)s * invf;
    g_cos[idx] = (float)cos((double)ang);
    g_sin[idx] = (float)sin((double)ang);
}

// ---------------- bf16 hi/lo pre-split kernels ----------------
static __device__ __forceinline__ void cvt_body(const float* __restrict__ src,
                                                u16* __restrict__ dh, u16* __restrict__ dl, int n4) {
    int i = blockIdx.x * blockDim.x + threadIdx.x;
    if (i >= n4) return;
    float4 v = ((const float4*)src)[i];
    u16 h0,h1,h2,h3,l0,l1,l2,l3;
    split1(v.x,h0,l0); split1(v.y,h1,l1); split1(v.z,h2,l2); split1(v.w,h3,l3);
    ((uint2*)dh)[i] = make_uint2((u32)h0 | ((u32)h1<<16), (u32)h2 | ((u32)h3<<16));
    ((uint2*)dl)[i] = make_uint2((u32)l0 | ((u32)l1<<16), (u32)l2 | ((u32)l3<<16));
}
__global__ void cvt_x_kernel (const float* __restrict__ s){ cvt_body(s, g_xh,  g_xl,  MTOT*DMODEL/4); }
__global__ void cvt_w_kernel (const float* __restrict__ s){ cvt_body(s, g_wh,  g_wl,  N_QKV*DMODEL/4); }
__global__ void cvt_wo_kernel(const float* __restrict__ s){ cvt_body(s, g_woh, g_wol, DMODEL*DMODEL/4); }

// ============================================================================
// bf16-split mma.sync GEMM: C[128,128] = A[m0:,K] * B[n0:,K]^T, K=1024.
// (R13 form — register prefetch, one __syncthreads per chunk; validated 1815us)
// ============================================================================
#define MM_BUF  40960
#define MM_SMEM 81920

__device__ __forceinline__ void mma_mainloop(
    const u16* __restrict__ Ah, const u16* __restrict__ Al,
    const u16* __restrict__ Bh, const u16* __restrict__ Bl,
    int m0, int n0, char* sm, uint32_t smb, float c[4][4][4])
{
    const int tid  = threadIdx.x;
    const int lane = tid & 31;
    const int wid  = tid >> 5;
    const int wm   = wid >> 2;       // 0..1
    const int wn   = wid & 3;        // 0..3
    const int r    = tid & 127;

    const uint4* gh;
    const uint4* gl;
    int sregion;
    if (tid < 128) {
        gh = (const uint4*)(Ah + (size_t)(m0 + r) * DMODEL);
        gl = (const uint4*)(Al + (size_t)(m0 + r) * DMODEL);
        sregion = 0;
    } else {
        gh = (const uint4*)(Bh + (size_t)(n0 + r) * DMODEL);
        gl = (const uint4*)(Bl + (size_t)(n0 + r) * DMODEL);
        sregion = 20480;
    }
    char* sdh_row = sm + sregion + r * 80;
    char* sdl_row = sdh_row + 10240;

    uint4 vh[4], vl[4];
#pragma unroll
    for (int i = 0; i < 4; ++i) { vh[i] = gh[i]; vl[i] = gl[i]; }
#pragma unroll
    for (int i = 0; i < 4; ++i) {
        *(uint4*)(sdh_row + i*16) = vh[i];
        *(uint4*)(sdl_row + i*16) = vl[i];
    }
    __syncthreads();

    const int arow = (lane & 7) + ((lane >> 3) & 1) * 8;
    const int acol = (lane >> 4) * 16;
    const int brow = (lane & 7) + ((lane >> 4) & 1) * 8;
    const int bcol = ((lane >> 3) & 1) * 16;
    const uint32_t aBase = smb + (uint32_t)((wm*64 + arow) * 80 + acol);
    const uint32_t bBase = smb + 20480 + (uint32_t)((wn*32 + brow) * 80 + bcol);

    int buf = 0;
    for (int ch = 0; ch < 32; ++ch) {
        const bool nxt = (ch + 1 < 32);
        if (nxt) {
#pragma unroll
            for (int i = 0; i < 4; ++i) {
                vh[i] = gh[(ch+1)*4 + i];
                vl[i] = gl[(ch+1)*4 + i];
            }
        }
        const uint32_t bo = (uint32_t)(buf * MM_BUF);
#pragma unroll
        for (int s = 0; s < 2; ++s) {
            uint32_t ah[4][4], al[4][4], bh[4][2], bl[4][2];
#pragma unroll
            for (int mt = 0; mt < 4; ++mt) {
                ldmx4(ah[mt], aBase + bo + mt*1280 + s*32);
                ldmx4(al[mt], aBase + bo + mt*1280 + s*32 + 10240);
            }
#pragma unroll
            for (int p = 0; p < 2; ++p) {
                uint32_t t4[4];
                ldmx4(t4, bBase + bo + p*1280 + s*32);
                bh[2*p][0] = t4[0]; bh[2*p][1] = t4[1];
                bh[2*p+1][0] = t4[2]; bh[2*p+1][1] = t4[3];
                ldmx4(t4, bBase + bo + p*1280 + s*32 + 10240);
                bl[2*p][0] = t4[0]; bl[2*p][1] = t4[1];
                bl[2*p+1][0] = t4[2]; bl[2*p+1][1] = t4[3];
            }
#pragma unroll
            for (int mt = 0; mt < 4; ++mt)
#pragma unroll
                for (int nt = 0; nt < 4; ++nt) {
                    mma_bf16(c[mt][nt], ah[mt], bh[nt]);
                    mma_bf16(c[mt][nt], ah[mt], bl[nt]);
                    mma_bf16(c[mt][nt], al[mt], bh[nt]);
                }
        }
        if (nxt) {
            char* dh = sdh_row + ((buf ^ 1) * MM_BUF);
            char* dl = sdl_row + ((buf ^ 1) * MM_BUF);
#pragma unroll
            for (int i = 0; i < 4; ++i) {
                *(uint4*)(dh + i*16) = vh[i];
                *(uint4*)(dl + i*16) = vl[i];
            }
            __syncthreads();
        }
        buf ^= 1;
    }
    __syncthreads();
}

// store fragments to Cs[128][132]
__device__ __forceinline__ void frag_to_cs(float* Cs, float c[4][4][4]) {
    const int tid = threadIdx.x;
    const int lane = tid & 31;
    const int wid = tid >> 5;
    const int wm = wid >> 2, wn = wid & 3;
    const int tr = lane >> 2, tc = (lane & 3) * 2;
#pragma unroll
    for (int mt = 0; mt < 4; ++mt)
#pragma unroll
        for (int nt = 0; nt < 4; ++nt) {
            int rr = wm*64 + mt*16 + tr;
            int cc = wn*32 + nt*8 + tc;
            *(float2*)&Cs[rr*132 + cc]       = make_float2(c[mt][nt][0], c[mt][nt][1]);
            *(float2*)&Cs[(rr+8)*132 + cc]   = make_float2(c[mt][nt][2], c[mt][nt][3]);
        }
    __syncthreads();
}

// ---------------- QKV GEMM (mma.sync) + RoPE epilogue ----------------
__global__ __launch_bounds__(256, 1) void qkv_mma_kernel()
{
    char* sm = dynsm;
    uint32_t smb = smem_u32(sm);

    float c[4][4][4];
#pragma unroll
    for (int a = 0; a < 4; ++a)
#pragma unroll
        for (int b = 0; b < 4; ++b)
#pragma unroll
            for (int d = 0; d < 4; ++d) c[a][b][d] = 0.f;

    const int m0 = blockIdx.x * 128;
    const int nt = blockIdx.y;                  // 0..23
    mma_mainloop(g_xh, g_xl, g_wh, g_wl, m0, nt * 128, sm, smb, c);

    float* Cs = (float*)sm;
    frag_to_cs(Cs, c);

    const int tid = threadIdx.x;
    const int sel   = nt >> 3;                  // 0=Q 1=K 2=V
    const int hbase = (nt & 7) * 2;
    float* dst = (sel == 0) ? g_q : ((sel == 1) ? g_k : g_v);

    for (int e = tid; e < 8192; e += 256) {
        int rr = e >> 6;
        int d  = (e & 63) * 2;                  // even col 0..126
        int m = m0 + rr;
        int b = m >> 11, s = m & 2047;
        float2 v = *(float2*)&Cs[rr*132 + d];
        int head = hbase + (d >> 6);
        int dloc = d & 63;
        if (sel < 2) {
            float2 p = *(float2*)&Cs[rr*132 + (d ^ 32)];
            int j = d & 31;
            float c0 = g_cos[s*32 + j],   c1 = g_cos[s*32 + j + 1];
            float s0 = g_sin[s*32 + j],   s1 = g_sin[s*32 + j + 1];
            if (dloc < 32) { v.x = v.x*c0 - p.x*s0; v.y = v.y*c1 - p.y*s1; }
            else           { v.x = v.x*c0 + p.x*s0; v.y = v.y*c1 + p.y*s1; }
        }
        *(float2*)&dst[(((size_t)b*NH + head)*SEQ + s)*DHD + dloc] = v;
    }
}

// ---------------- out_proj (mma.sync): out = AO @ wo^T ----------------
__global__ __launch_bounds__(256, 1) void out_proj_mma_kernel(float* __restrict__ out)
{
    char* sm = dynsm;
    uint32_t smb = smem_u32(sm);

    float c[4][4][4];
#pragma unroll
    for (int a = 0; a < 4; ++a)
#pragma unroll
        for (int b = 0; b < 4; ++b)
#pragma unroll
            for (int d = 0; d < 4; ++d) c[a][b][d] = 0.f;

    const int m0 = blockIdx.x * 128;
    const int n0 = blockIdx.y * 128;
    mma_mainloop(g_aoh, g_aol, g_woh, g_wol, m0, n0, sm, smb, c);

    float* Cs = (float*)sm;
    frag_to_cs(Cs, c);

    const int tid = threadIdx.x;
    for (int e = tid; e < 4096; e += 256) {
        int rr = e >> 5;
        int d4 = (e & 31) * 4;
        *(float4*)&out[(size_t)(m0 + rr)*DMODEL + n0 + d4] = *(float4*)&Cs[rr*132 + d4];
    }
}

// ============================================================================
// Flash attention on mma.sync (causal). BM=128 (8 warps x m16), KV tile 64.
// R13 structure + V stored row-major [c][d] with vectorized stores and
// B-fragments via ldmatrix.x4.trans (validated correct in R15).
// smem rows stride 144B (ldmatrix banks 4r mod 32 -> conflict-free).
// ============================================================================
#define AQH 0
#define AQL 18432
#define AKH 36864
#define AKL 46080
#define AVH 55296
#define AVL 64512
#define ATTN_SMEM 73728

__global__ __launch_bounds__(256, 1) void attn_mma_kernel()
{
    char* sm = dynsm;
    uint32_t smb = smem_u32(sm);

    const int tid  = threadIdx.x;
    const int lane = tid & 31;
    const int wid  = tid >> 5;          // 0..7, warp owns q-rows 16*wid..+15
    const int qt   = blockIdx.x;        // 0..15 (128-row q tile)
    const int bh   = blockIdx.y;        // 0..63

    const float* Qg = g_q + ((size_t)bh * SEQ + qt * 128) * DHD;
    const float* Kg = g_k + (size_t)bh * SEQ * DHD;
    const float* Vg = g_v + (size_t)bh * SEQ * DHD;

    // ---- load Q tile 128x64, scale by 1/8, split hi/lo into smem ----
    for (int slot = tid; slot < 2048; slot += 256) {
        int r  = slot >> 4;
        int f4 = slot & 15;
        float4 v = ((const float4*)Qg)[slot];
        v.x *= 0.125f; v.y *= 0.125f; v.z *= 0.125f; v.w *= 0.125f;
        u32 h0, l0, h1, l1;
        pksplit(v.x, v.y, h0, l0);
        pksplit(v.z, v.w, h1, l1);
        *(uint2*)(sm + AQH + r*144 + f4*8) = make_uint2(h0, h1);
        *(uint2*)(sm + AQL + r*144 + f4*8) = make_uint2(l0, l1);
    }

    // ldmatrix lane addressing
    const int arow = (lane & 7) + ((lane >> 3) & 1) * 8;
    const int acol = (lane >> 4) * 16;
    const int brow = (lane & 7) + ((lane >> 4) & 1) * 8;
    const int bcol = ((lane >> 3) & 1) * 16;
    const uint32_t aBaseH = smb + AQH + (uint32_t)((wid*16 + arow)*144 + acol);
    const uint32_t aBaseL = aBaseH + (AQL - AQH);
    const uint32_t kBase  = smb + AKH + (uint32_t)(brow*144 + bcol);
    // trans-ldmatrix addressing for V[c][d]: row = c (k), col-block = d (n)
    const int vrow = (lane & 7) + ((lane >> 3) & 1) * 8;
    const int vcol = ((lane >> 4) & 1) * 16;
    const uint32_t vBase  = smb + AVH + (uint32_t)(vrow*144 + vcol);

    const int rowTop = qt*128 + wid*16;
    const int r0     = rowTop + (lane >> 2);

    float mi0 = -INFINITY, mi1 = -INFINITY, li0 = 0.f, li1 = 0.f;
    float accO[8][4];
#pragma unroll
    for (int j = 0; j < 8; ++j)
#pragma unroll
        for (int d = 0; d < 4; ++d) accO[j][d] = 0.f;

    const int nkt = 2*qt + 2;
    for (int kt = 0; kt < nkt; ++kt) {
        __syncthreads();     // prior tile's smem reads complete
        // ---- load K and V tiles (64x64 fp32), split; both row-major ----
        for (int slot = tid; slot < 2048; slot += 256) {
            int cc = (slot & 1023) >> 4;
            int f4 = slot & 15;
            if (slot < 1024) {
                float4 v = ((const float4*)(Kg + (size_t)(kt*64 + cc)*DHD))[f4];
                u32 h0, l0, h1, l1;
                pksplit(v.x, v.y, h0, l0);
                pksplit(v.z, v.w, h1, l1);
                *(uint2*)(sm + AKH + cc*144 + f4*8) = make_uint2(h0, h1);
                *(uint2*)(sm + AKL + cc*144 + f4*8) = make_uint2(l0, l1);
            } else {
                float4 v = ((const float4*)(Vg + (size_t)(kt*64 + cc)*DHD))[f4];
                u32 h0, l0, h1, l1;
                pksplit(v.x, v.y, h0, l0);
                pksplit(v.z, v.w, h1, l1);
                *(uint2*)(sm + AVH + cc*144 + f4*8) = make_uint2(h0, h1);
                *(uint2*)(sm + AVL + cc*144 + f4*8) = make_uint2(l0, l1);
            }
        }
        __syncthreads();

        // ---- S = (Q/8) K^T : 3-term bf16 ----
        float accS[8][4];
#pragma unroll
        for (int j = 0; j < 8; ++j)
#pragma unroll
            for (int d = 0; d < 4; ++d) accS[j][d] = 0.f;

#pragma unroll
        for (int s = 0; s < 4; ++s) {
            u32 ah[4], al[4];
            ldmx4(ah, aBaseH + s*32);
            ldmx4(al, aBaseL + s*32);
#pragma unroll
            for (int g = 0; g < 4; ++g) {
                u32 th[4], tl[4];
                ldmx4(th, kBase + g*2304 + s*32);
                ldmx4(tl, kBase + (AKL-AKH) + g*2304 + s*32);
                mma_bf16(accS[2*g],   ah, th);
                mma_bf16(accS[2*g],   ah, tl);
                mma_bf16(accS[2*g],   al, th);
                mma_bf16(accS[2*g+1], ah, th+2);
                mma_bf16(accS[2*g+1], ah, tl+2);
                mma_bf16(accS[2*g+1], al, th+2);
            }
        }

        // ---- causal mask (only tiles crossing the diagonal) ----
        if (kt*64 + 63 > rowTop) {
#pragma unroll
            for (int j = 0; j < 8; ++j) {
                int cb = kt*64 + j*8 + 2*(lane & 3);
                if (cb     > r0)     accS[j][0] = -INFINITY;
                if (cb + 1 > r0)     accS[j][1] = -INFINITY;
                if (cb     > r0 + 8) accS[j][2] = -INFINITY;
                if (cb + 1 > r0 + 8) accS[j][3] = -INFINITY;
            }
        }

        // ---- online softmax on fragments (rows r0, r0+8) ----
        float mx0 = -INFINITY, mx1 = -INFINITY;
#pragma unroll
        for (int j = 0; j < 8; ++j) {
            mx0 = fmaxf(mx0, fmaxf(accS[j][0], accS[j][1]));
            mx1 = fmaxf(mx1, fmaxf(accS[j][2], accS[j][3]));
        }
        mx0 = fmaxf(mx0, __shfl_xor_sync(0xffffffffu, mx0, 1));
        mx0 = fmaxf(mx0, __shfl_xor_sync(0xffffffffu, mx0, 2));
        mx1 = fmaxf(mx1, __shfl_xor_sync(0xffffffffu, mx1, 1));
        mx1 = fmaxf(mx1, __shfl_xor_sync(0xffffffffu, mx1, 2));
        float nm0 = fmaxf(mi0, mx0), nm1 = fmaxf(mi1, mx1);
        float a0 = __expf(mi0 - nm0), a1 = __expf(mi1 - nm1);
        mi0 = nm0; mi1 = nm1;
        float s0 = 0.f, s1 = 0.f;
#pragma unroll
        for (int j = 0; j < 8; ++j) {
            accS[j][0] = __expf(accS[j][0] - nm0); s0 += accS[j][0];
            accS[j][1] = __expf(accS[j][1] - nm0); s0 += accS[j][1];
            accS[j][2] = __expf(accS[j][2] - nm1); s1 += accS[j][2];
            accS[j][3] = __expf(accS[j][3] - nm1); s1 += accS[j][3];
        }
        s0 += __shfl_xor_sync(0xffffffffu, s0, 1);
        s0 += __shfl_xor_sync(0xffffffffu, s0, 2);
        s1 += __shfl_xor_sync(0xffffffffu, s1, 1);
        s1 += __shfl_xor_sync(0xffffffffu, s1, 2);
        li0 = li0 * a0 + s0;
        li1 = li1 * a1 + s1;
#pragma unroll
        for (int j = 0; j < 8; ++j) {
            accO[j][0] *= a0; accO[j][1] *= a0;
            accO[j][2] *= a1; accO[j][3] *= a1;
        }

        // ---- O += P @ V : P from registers, V B-frags via ldmatrix.trans ----
#pragma unroll
        for (int t = 0; t < 4; ++t) {
            u32 ph[4], pl[4];
            pksplit(accS[2*t][0],   accS[2*t][1],   ph[0], pl[0]);
            pksplit(accS[2*t][2],   accS[2*t][3],   ph[1], pl[1]);
            pksplit(accS[2*t+1][0], accS[2*t+1][1], ph[2], pl[2]);
            pksplit(accS[2*t+1][2], accS[2*t+1][3], ph[3], pl[3]);
#pragma unroll
            for (int g = 0; g < 4; ++g) {
                u32 th[4], tl[4];
                ldmx4t(th, vBase + t*2304 + g*32);
                ldmx4t(tl, vBase + (AVL-AVH) + t*2304 + g*32);
                mma_bf16(accO[2*g],   ph, th);
                mma_bf16(accO[2*g],   ph, tl);
                mma_bf16(accO[2*g],   pl, th);
                mma_bf16(accO[2*g+1], ph, th+2);
                mma_bf16(accO[2*g+1], ph, tl+2);
                mma_bf16(accO[2*g+1], pl, th+2);
            }
        }
    }

    // ---- epilogue: normalize, split to bf16 hi/lo for out_proj ----
    const float inv0 = 1.0f / li0, inv1 = 1.0f / li1;
    const int b = bh >> 4, h = bh & 15;
    const int srow = qt*128 + wid*16 + (lane >> 2);
    const size_t base0 = ((size_t)b*SEQ + srow)*DMODEL + h*DHD + 2*(lane & 3);
    const size_t base1 = base0 + (size_t)8*DMODEL;
#pragma unroll
    for (int j = 0; j < 8; ++j) {
        u32 hh, ll;
        pksplit(accO[j][0]*inv0, accO[j][1]*inv0, hh, ll);
        *(u32*)&g_aoh[base0 + j*8] = hh;
        *(u32*)&g_aol[base0 + j*8] = ll;
        pksplit(accO[j][2]*inv1, accO[j][3]*inv1, hh, ll);
        *(u32*)&g_aoh[base1 + j*8] = hh;
        *(u32*)&g_aol[base1 + j*8] = ll;
    }
}

// ---------------- launch ----------------
extern "C" void kernel_launch(void* const* d_in, const int* in_sizes, int n_in,
                              void* d_out, int out_size)
{
    (void)in_sizes; (void)n_in; (void)out_size;
    const float* x    = (const float*)d_in[0];
    const float* qkvw = (const float*)d_in[1];
    const float* wo   = (const float*)d_in[2];
    float*       out  = (float*)d_out;

    rope_table_kernel<<<(SEQ*32 + 255)/256, 256>>>();
    cvt_x_kernel <<<(MTOT*DMODEL/4   + 255)/256, 256>>>(x);
    cvt_w_kernel <<<(N_QKV*DMODEL/4  + 255)/256, 256>>>(qkvw);
    cvt_wo_kernel<<<(DMODEL*DMODEL/4 + 255)/256, 256>>>(wo);

    cudaFuncSetAttribute(qkv_mma_kernel, cudaFuncAttributeMaxDynamicSharedMemorySize, MM_SMEM);
    qkv_mma_kernel<<<dim3(MTOT/128, N_QKV/128), 256, MM_SMEM>>>();

    cudaFuncSetAttribute(attn_mma_kernel, cudaFuncAttributeMaxDynamicSharedMemorySize, ATTN_SMEM);
    attn_mma_kernel<<<dim3(SEQ/128, BATCH*NH), 256, ATTN_SMEM>>>();

    cudaFuncSetAttribute(out_proj_mma_kernel, cudaFuncAttributeMaxDynamicSharedMemorySize, MM_SMEM);
    out_proj_mma_kernel<<<dim3(MTOT/128, DMODEL/128), 256, MM_SMEM>>>(out);
}